// round 14
// baseline (speedup 1.0000x reference)
#include <cuda_runtime.h>
#include <cuda_fp16.h>
#include <cstdint>

// ---------------- problem constants ----------------
#define BATCH   16
#define C_IN    64
#define C_OUT   128
#define HH      128
#define WW      128
#define PW      130              // padded width/height
#define PIX_PAD (PW*PW)
#define XT_ROWS 16904
#define NTAP    9

// ---- output tile: 2 rows x 64 cols = 128 pixels (M) ----
#define TR      2
#define TC      64
#define AH      4                // window rows  (TR + 2)
#define AW      66               // window cols  (TC + 2)
#define A_ROWS  (AH * AW)        // 264 pixel-rows

// ---- smem layout (dynamic) ----
#define ROWB     144
#define A_BYTES  (A_ROWS * ROWB)            // 38016
#define B_TILE   (128 * ROWB)               // 18432
#define NSTAGE   3
#define SMEM_B0  A_BYTES
#define SMEM_MAIN (A_BYTES + NSTAGE * B_TILE)   // 93312

#define NTHREADS 128

// ---------------- device globals (scratch) ----------------
__device__ __half g_xt[(size_t)BATCH * XT_ROWS * C_IN];   // [b][pixel][ic]
__device__ __half g_wt[NTAP * C_OUT * C_IN];              // [tap][oc][ic]

// ---------------- ptx helpers ----------------
__device__ __forceinline__ uint32_t smem_u32(const void* p) {
    uint32_t a;
    asm("{ .reg .u64 t; cvta.to.shared.u64 t, %1; cvt.u32.u64 %0, t; }" : "=r"(a) : "l"(p));
    return a;
}
__device__ __forceinline__ void cp_async16(uint32_t dst, const void* src) {
    asm volatile("cp.async.cg.shared.global [%0], [%1], 16;" :: "r"(dst), "l"(src));
}
__device__ __forceinline__ void cp_commit() {
    asm volatile("cp.async.commit_group;" ::: "memory");
}
template <int N>
__device__ __forceinline__ void cp_wait() {
    asm volatile("cp.async.wait_group %0;" :: "n"(N) : "memory");
}
__device__ __forceinline__ void ldm_x4(uint32_t& r0, uint32_t& r1, uint32_t& r2, uint32_t& r3, uint32_t addr) {
    asm volatile("ldmatrix.sync.aligned.m8n8.x4.shared.b16 {%0,%1,%2,%3}, [%4];"
                 : "=r"(r0), "=r"(r1), "=r"(r2), "=r"(r3) : "r"(addr));
}
__device__ __forceinline__ void mma16816(float* c, const uint32_t* a, uint32_t b0, uint32_t b1) {
    asm volatile("mma.sync.aligned.m16n8k16.row.col.f32.f16.f16.f32 "
                 "{%0,%1,%2,%3}, {%4,%5,%6,%7}, {%8,%9}, {%0,%1,%2,%3};"
                 : "+f"(c[0]), "+f"(c[1]), "+f"(c[2]), "+f"(c[3])
                 : "r"(a[0]), "r"(a[1]), "r"(a[2]), "r"(a[3]), "r"(b0), "r"(b1));
}

// ---------------- fused prep: weights + x transform (proven) ----------------
__global__ __launch_bounds__(256)
void prep_fused(const float* __restrict__ x, const float* __restrict__ w) {
    __shared__ float buf[64][133];
    const int tid = threadIdx.x;

    if (blockIdx.y == BATCH) {
        for (int idx = blockIdx.x * 256 + tid; idx < NTAP * C_OUT * C_IN; idx += PW * 256) {
            int ic  = idx & 63;
            int oc  = (idx >> 6) & 127;
            int tap = idx >> 13;
            int i = oc >> 3, p = oc & 7;
            int j = ic >> 3, q = ic & 7;
            int kh = tap / 3, kw = tap % 3;
            g_wt[idx] = __float2half_rn(w[i * 4608 + j * 576 + p * 72 + q * 9 + kh * 3 + kw]);
        }
        return;
    }

    const int hp = blockIdx.x;   // 0..129
    const int b  = blockIdx.y;
    __half* dst = g_xt + ((size_t)b * XT_ROWS + (size_t)hp * PW) * C_IN;

    if (hp == 0 || hp == PW - 1) {
        uint4 z = make_uint4(0, 0, 0, 0);
        for (int idx = tid; idx < PW * C_IN / 8; idx += 256) ((uint4*)dst)[idx] = z;
        if (hp == PW - 1) {
            uint4* g = (uint4*)(g_xt + ((size_t)b * XT_ROWS + PIX_PAD) * C_IN);
            for (int idx = tid; idx < 4 * C_IN / 8; idx += 256) g[idx] = z;
        }
        return;
    }
    const float* src = x + ((size_t)b * C_IN * HH + (size_t)(hp - 1)) * WW;
    for (int idx = tid; idx < C_IN * 32; idx += 256) {
        int ic = idx >> 5, f4 = idx & 31;
        float4 v = *(const float4*)(src + (size_t)ic * HH * WW + f4 * 4);
        buf[ic][1 + f4 * 4 + 0] = v.x;
        buf[ic][1 + f4 * 4 + 1] = v.y;
        buf[ic][1 + f4 * 4 + 2] = v.z;
        buf[ic][1 + f4 * 4 + 3] = v.w;
    }
    __syncthreads();
    __half2* d2 = (__half2*)dst;
    for (int idx = tid; idx < PW * 32; idx += 256) {
        int wp = idx >> 5, icp = idx & 31;
        float v0 = 0.0f, v1 = 0.0f;
        if (wp != 0 && wp != PW - 1) {
            v0 = buf[icp * 2 + 0][wp];
            v1 = buf[icp * 2 + 1][wp];
        }
        d2[(size_t)wp * 32 + icp] = __floats2half2_rn(v0, v1);
    }
}

// ---------------- B-tap loader (cp.async, one commit group) ----------------
__device__ __forceinline__ void load_B(uint32_t sB, int tap, int tid) {
    const __half* bsrc = g_wt + (size_t)tap * C_OUT * C_IN;
    #pragma unroll
    for (int i = 0; i < 8; ++i) {
        int idx = tid + i * NTHREADS;
        int oc = idx >> 3, c = idx & 7;
        cp_async16(sB + oc * ROWB + c * 16, bsrc + (size_t)oc * C_IN + c * 8);
    }
    cp_commit();
}

// ---------------- main kernel: R8 + software-pipelined fragments ----------------
__global__ __launch_bounds__(NTHREADS, 2)
void oct_mma_kernel(const float* __restrict__ bias, float* __restrict__ out) {
    extern __shared__ char smem[];
    __shared__ float bias_s[C_OUT];
    const uint32_t sb = smem_u32(smem);
    const int tid  = threadIdx.x;
    const int wid  = tid >> 5;
    const int lane = tid & 31;
    const int mwarp = wid & 1;        // output row within 2-row tile
    const int nwarp = wid >> 1;       // oc half

    const int tc = blockIdx.x & 1;    // tile col (64 px)
    const int tr = blockIdx.x >> 1;   // tile row (2 px)
    const int b  = blockIdx.y;        // batch

    const int R0 = tr * TR;
    const int C0 = tc * TC;

    bias_s[tid] = bias[tid];

    // ---- group 0: A window rows (once): 264 rows x 128B from g_xt ----
    {
        const __half* xtb = g_xt + ((size_t)b * XT_ROWS) * C_IN;
        for (int idx = tid; idx < A_ROWS * 8; idx += NTHREADS) {
            int m = idx >> 3, c = idx & 7;
            int r = m / AW, col = m - r * AW;
            const __half* src = xtb + ((size_t)(R0 + r) * PW + (C0 + col)) * C_IN + c * 8;
            cp_async16(sb + m * ROWB + c * 16, src);
        }
        cp_commit();
    }
    // ---- groups 1,2: B taps 0,1 ----
    load_B(sb + SMEM_B0 + 0 * B_TILE, 0, tid);
    load_B(sb + SMEM_B0 + 1 * B_TILE, 1, tid);

    float acc[4][8][4];
    #pragma unroll
    for (int mf = 0; mf < 4; ++mf)
        #pragma unroll
        for (int nf = 0; nf < 8; ++nf)
            #pragma unroll
            for (int c = 0; c < 4; ++c) acc[mf][nf][c] = 0.0f;

    // lane-constant ldmatrix offsets
    const int a_row_local = ((lane >> 3) & 1) * 8 + (lane & 7);
    const uint32_t a_off = (uint32_t)(mwarp * AW + a_row_local) * ROWB + (lane >> 4) * 16;
    const int b_row = ((lane >> 4) << 3) + (lane & 7);
    const uint32_t b_off = (uint32_t)(nwarp * 64 + b_row) * ROWB + ((lane >> 3) & 1) * 16;

    const int shifts[NTAP] = {0, 1, 2, AW, AW + 1, AW + 2, 2 * AW, 2 * AW + 1, 2 * AW + 2};

    uint32_t a_cur[4][4];   // A fragments for current ks
    uint32_t b_cur[4];      // B fragment for current (ks, nf2)

    #pragma unroll 1
    for (int t = 0; t < NTAP; ++t) {
        if (t < NTAP - 1) cp_wait<1>(); else cp_wait<0>();
        __syncthreads();
        if (t + 2 < NTAP)
            load_B(sb + SMEM_B0 + (uint32_t)((t + 2) % NSTAGE) * B_TILE, t + 2, tid);

        const uint32_t aB = sb + a_off + (uint32_t)shifts[t] * ROWB;
        const uint32_t bB = sb + SMEM_B0 + (uint32_t)(t % NSTAGE) * B_TILE + b_off;

        if (t == 0) {
            #pragma unroll
            for (int mf = 0; mf < 4; ++mf)
                ldm_x4(a_cur[mf][0], a_cur[mf][1], a_cur[mf][2], a_cur[mf][3],
                       aB + mf * 16 * ROWB);
        }
        // B fragment for (ks=0, nf2=0) of this tap (B(t) guaranteed landed)
        ldm_x4(b_cur[0], b_cur[1], b_cur[2], b_cur[3], bB);

        #pragma unroll
        for (int ks = 0; ks < 4; ++ks) {
            uint32_t a_nxt[4][4];
            #pragma unroll
            for (int nf2 = 0; nf2 < 4; ++nf2) {
                uint32_t b_nxt[4];
                // ---- prefetch next B fragment ----
                if (nf2 < 3) {
                    ldm_x4(b_nxt[0], b_nxt[1], b_nxt[2], b_nxt[3],
                           bB + (nf2 + 1) * 16 * ROWB + ks * 32);
                } else if (ks < 3) {
                    ldm_x4(b_nxt[0], b_nxt[1], b_nxt[2], b_nxt[3],
                           bB + (ks + 1) * 32);
                }
                // ---- prefetch next A fragments (once per ks, early) ----
                if (nf2 == 0) {
                    if (ks < 3) {
                        #pragma unroll
                        for (int mf = 0; mf < 4; ++mf)
                            ldm_x4(a_nxt[mf][0], a_nxt[mf][1], a_nxt[mf][2], a_nxt[mf][3],
                                   aB + mf * 16 * ROWB + (ks + 1) * 32);
                    } else if (t < NTAP - 1) {
                        // next tap's ks=0 A fragments (A smem is static across taps)
                        const uint32_t aN = sb + a_off + (uint32_t)shifts[t + 1] * ROWB;
                        #pragma unroll
                        for (int mf = 0; mf < 4; ++mf)
                            ldm_x4(a_nxt[mf][0], a_nxt[mf][1], a_nxt[mf][2], a_nxt[mf][3],
                                   aN + mf * 16 * ROWB);
                    }
                }
                // ---- 8 MMAs with current fragments ----
                #pragma unroll
                for (int mf = 0; mf < 4; ++mf) {
                    mma16816(acc[mf][nf2 * 2 + 0], a_cur[mf], b_cur[0], b_cur[1]);
                    mma16816(acc[mf][nf2 * 2 + 1], a_cur[mf], b_cur[2], b_cur[3]);
                }
                // rotate B
                if (!(ks == 3 && nf2 == 3)) {
                    b_cur[0] = b_nxt[0]; b_cur[1] = b_nxt[1];
                    b_cur[2] = b_nxt[2]; b_cur[3] = b_nxt[3];
                }
            }
            // rotate A
            #pragma unroll
            for (int mf = 0; mf < 4; ++mf) {
                a_cur[mf][0] = a_nxt[mf][0]; a_cur[mf][1] = a_nxt[mf][1];
                a_cur[mf][2] = a_nxt[mf][2]; a_cur[mf][3] = a_nxt[mf][3];
            }
        }
    }
    __syncthreads();   // protect smem reuse by epilogue

    // ---- epilogue: transpose (bias folded) through smem -> coalesced stores ----
    float* so = (float*)smem;   // [oc][136]
    #pragma unroll
    for (int mf = 0; mf < 4; ++mf)
        #pragma unroll
        for (int nf = 0; nf < 8; ++nf)
            #pragma unroll
            for (int c = 0; c < 4; ++c) {
                int oc = nwarp * 64 + nf * 8 + (lane & 3) * 2 + (c & 1);
                int m  = mwarp * 64 + mf * 16 + (lane >> 2) + (c & 2) * 4;
                so[oc * 136 + m] = acc[mf][nf][c] + bias_s[oc];
            }
    __syncthreads();

    const int m_ = tid;                  // 0..127 : pixel index
    const int h  = R0 + (m_ >> 6);
    const int w_ = C0 + (m_ & 63);
    float* ob = out + ((size_t)b * C_OUT) * HH * WW + (size_t)h * WW + w_;
    #pragma unroll 8
    for (int oc = 0; oc < C_OUT; ++oc)
        ob[(size_t)oc * HH * WW] = so[oc * 136 + m_];
}

// ---------------- launch ----------------
extern "C" void kernel_launch(void* const* d_in, const int* in_sizes, int n_in,
                              void* d_out, int out_size) {
    const float* x    = (const float*)d_in[0];
    const float* wgt  = (const float*)d_in[1];
    const float* bias = (const float*)d_in[2];
    float* out = (float*)d_out;

    {
        dim3 g(PW, BATCH + 1);          // y==BATCH rows do weight repack
        prep_fused<<<g, 256>>>(x, wgt);
    }
    cudaFuncSetAttribute(oct_mma_kernel, cudaFuncAttributeMaxDynamicSharedMemorySize, SMEM_MAIN);
    {
        dim3 g((HH / TR) * (WW / TC), BATCH);   // 128 tiles x 16 batches
        oct_mma_kernel<<<g, NTHREADS, SMEM_MAIN>>>(bias, out);
    }
}

// round 16
// speedup vs baseline: 1.1349x; 1.1349x over previous
#include <cuda_runtime.h>
#include <cuda_fp16.h>
#include <cstdint>
#include <cstring>

// ---------------- problem constants ----------------
#define BATCH   16
#define C_IN    64
#define C_OUT   128
#define HH      128
#define WW      128
#define PW      130              // padded width/height
#define PIX_PAD (PW*PW)
#define XT_ROWS 16904
#define NTAP    9

// ---- output tile: 2 rows x 64 cols = 128 pixels (M) ----
#define TR      2
#define TC      64
#define AH      4                // window rows  (TR + 2)
#define AW      66               // window cols  (TC + 2)
#define A_ROWS  (AH * AW)        // 264 pixel-rows

// ---- smem layout (dynamic) ----
#define ROWB     144
#define A_BYTES  (A_ROWS * ROWB)            // 38016
#define B_TILE   (128 * ROWB)               // 18432
#define NSTAGE   3
#define SMEM_B0  A_BYTES
#define SMEM_MAIN (A_BYTES + NSTAGE * B_TILE)   // 93312

#define NTHREADS 128

// ---------------- device globals (scratch) ----------------
__device__ __half g_xt[(size_t)BATCH * XT_ROWS * C_IN];   // [b][pixel][ic]
__device__ __half g_wt[NTAP * C_OUT * C_IN];              // [tap][oc][ic]

// ---------------- ptx helpers ----------------
__device__ __forceinline__ uint32_t smem_u32(const void* p) {
    uint32_t a;
    asm("{ .reg .u64 t; cvta.to.shared.u64 t, %1; cvt.u32.u64 %0, t; }" : "=r"(a) : "l"(p));
    return a;
}
__device__ __forceinline__ void cp_async16(uint32_t dst, const void* src) {
    asm volatile("cp.async.cg.shared.global [%0], [%1], 16;" :: "r"(dst), "l"(src));
}
__device__ __forceinline__ void cp_commit() {
    asm volatile("cp.async.commit_group;" ::: "memory");
}
template <int N>
__device__ __forceinline__ void cp_wait() {
    asm volatile("cp.async.wait_group %0;" :: "n"(N) : "memory");
}
__device__ __forceinline__ void ldm_x4(uint32_t& r0, uint32_t& r1, uint32_t& r2, uint32_t& r3, uint32_t addr) {
    asm volatile("ldmatrix.sync.aligned.m8n8.x4.shared.b16 {%0,%1,%2,%3}, [%4];"
                 : "=r"(r0), "=r"(r1), "=r"(r2), "=r"(r3) : "r"(addr));
}
__device__ __forceinline__ void mma16816(float* c, const uint32_t* a, uint32_t b0, uint32_t b1) {
    asm volatile("mma.sync.aligned.m16n8k16.row.col.f32.f16.f16.f32 "
                 "{%0,%1,%2,%3}, {%4,%5,%6,%7}, {%8,%9}, {%0,%1,%2,%3};"
                 : "+f"(c[0]), "+f"(c[1]), "+f"(c[2]), "+f"(c[3])
                 : "r"(a[0]), "r"(a[1]), "r"(a[2]), "r"(a[3]), "r"(b0), "r"(b1));
}
__device__ __forceinline__ uint32_t h2_bits(__half2 h) {
    uint32_t u;
    memcpy(&u, &h, 4);
    return u;
}

// ---------------- fused prep: weights + x transform (vectorized stores) ----------------
__global__ __launch_bounds__(256)
void prep_fused(const float* __restrict__ x, const float* __restrict__ w) {
    __shared__ float buf[64][133];
    const int tid = threadIdx.x;

    if (blockIdx.y == BATCH) {
        for (int idx = blockIdx.x * 256 + tid; idx < NTAP * C_OUT * C_IN; idx += PW * 256) {
            int ic  = idx & 63;
            int oc  = (idx >> 6) & 127;
            int tap = idx >> 13;
            int i = oc >> 3, p = oc & 7;
            int j = ic >> 3, q = ic & 7;
            int kh = tap / 3, kw = tap % 3;
            g_wt[idx] = __float2half_rn(w[i * 4608 + j * 576 + p * 72 + q * 9 + kh * 3 + kw]);
        }
        return;
    }

    const int hp = blockIdx.x;   // 0..129
    const int b  = blockIdx.y;
    __half* dst = g_xt + ((size_t)b * XT_ROWS + (size_t)hp * PW) * C_IN;

    if (hp == 0 || hp == PW - 1) {
        uint4 z = make_uint4(0, 0, 0, 0);
        for (int idx = tid; idx < PW * C_IN / 8; idx += 256) ((uint4*)dst)[idx] = z;
        if (hp == PW - 1) {
            uint4* g = (uint4*)(g_xt + ((size_t)b * XT_ROWS + PIX_PAD) * C_IN);
            for (int idx = tid; idx < 4 * C_IN / 8; idx += 256) g[idx] = z;
        }
        return;
    }
    const float* src = x + ((size_t)b * C_IN * HH + (size_t)(hp - 1)) * WW;
    for (int idx = tid; idx < C_IN * 32; idx += 256) {
        int ic = idx >> 5, f4 = idx & 31;
        float4 v = *(const float4*)(src + (size_t)ic * HH * WW + f4 * 4);
        buf[ic][1 + f4 * 4 + 0] = v.x;
        buf[ic][1 + f4 * 4 + 1] = v.y;
        buf[ic][1 + f4 * 4 + 2] = v.z;
        buf[ic][1 + f4 * 4 + 3] = v.w;
    }
    __syncthreads();
    // transposed write, 16B stores: each idx = (pixel wp, channel-group icg of 8)
    for (int idx = tid; idx < PW * 8; idx += 256) {
        int wp = idx >> 3, icg = idx & 7;
        uint4 v;
        if (wp == 0 || wp == PW - 1) {
            v = make_uint4(0, 0, 0, 0);
        } else {
            const int ic0 = icg * 8;
            v.x = h2_bits(__floats2half2_rn(buf[ic0 + 0][wp], buf[ic0 + 1][wp]));
            v.y = h2_bits(__floats2half2_rn(buf[ic0 + 2][wp], buf[ic0 + 3][wp]));
            v.z = h2_bits(__floats2half2_rn(buf[ic0 + 4][wp], buf[ic0 + 5][wp]));
            v.w = h2_bits(__floats2half2_rn(buf[ic0 + 6][wp], buf[ic0 + 7][wp]));
        }
        *(uint4*)(dst + (size_t)wp * C_IN + icg * 8) = v;
    }
}

// ---------------- B-tap loader (cp.async, one commit group) ----------------
__device__ __forceinline__ void load_B(uint32_t sB, int tap, int tid) {
    const __half* bsrc = g_wt + (size_t)tap * C_OUT * C_IN;
    #pragma unroll
    for (int i = 0; i < 8; ++i) {
        int idx = tid + i * NTHREADS;
        int oc = idx >> 3, c = idx & 7;
        cp_async16(sB + oc * ROWB + c * 16, bsrc + (size_t)oc * C_IN + c * 8);
    }
    cp_commit();
}

// ---------------- main kernel: R8 verbatim (4 warps, 64x64 warp tiles) ----------------
__global__ __launch_bounds__(NTHREADS, 2)
void oct_mma_kernel(const float* __restrict__ bias, float* __restrict__ out) {
    extern __shared__ char smem[];
    __shared__ float bias_s[C_OUT];
    const uint32_t sb = smem_u32(smem);
    const int tid  = threadIdx.x;
    const int wid  = tid >> 5;
    const int lane = tid & 31;
    const int mwarp = wid & 1;        // m half: output row 0 or 1 (64 px each)
    const int nwarp = wid >> 1;       // n half: oc 0-63 or 64-127

    const int tc = blockIdx.x & 1;    // tile col (64 px)
    const int tr = blockIdx.x >> 1;   // tile row (2 px), 0..63
    const int b  = blockIdx.y;        // batch

    const int R0 = tr * TR;
    const int C0 = tc * TC;

    bias_s[tid] = bias[tid];

    // ---- group 0: A window rows (once): 264 rows x 128B from g_xt ----
    {
        const __half* xtb = g_xt + ((size_t)b * XT_ROWS) * C_IN;
        for (int idx = tid; idx < A_ROWS * 8; idx += NTHREADS) {
            int m = idx >> 3, c = idx & 7;
            int r = m / AW, col = m - r * AW;
            const __half* src = xtb + ((size_t)(R0 + r) * PW + (C0 + col)) * C_IN + c * 8;
            cp_async16(sb + m * ROWB + c * 16, src);
        }
        cp_commit();
    }
    // ---- groups 1,2: B taps 0,1 ----
    load_B(sb + SMEM_B0 + 0 * B_TILE, 0, tid);
    load_B(sb + SMEM_B0 + 1 * B_TILE, 1, tid);

    float acc[4][8][4];
    #pragma unroll
    for (int mf = 0; mf < 4; ++mf)
        #pragma unroll
        for (int nf = 0; nf < 8; ++nf)
            #pragma unroll
            for (int c = 0; c < 4; ++c) acc[mf][nf][c] = 0.0f;

    // lane-constant ldmatrix offsets
    const int a_row_local = ((lane >> 3) & 1) * 8 + (lane & 7);
    const uint32_t a_off = (uint32_t)(mwarp * AW + a_row_local) * ROWB + (lane >> 4) * 16;
    const int b_row = ((lane >> 4) << 3) + (lane & 7);
    const uint32_t b_off = (uint32_t)(nwarp * 64 + b_row) * ROWB + ((lane >> 3) & 1) * 16;

    const int shifts[NTAP] = {0, 1, 2, AW, AW + 1, AW + 2, 2 * AW, 2 * AW + 1, 2 * AW + 2};

    #pragma unroll
    for (int t = 0; t < NTAP; ++t) {
        if (t < NTAP - 1) cp_wait<1>(); else cp_wait<0>();
        __syncthreads();
        if (t + 2 < NTAP)
            load_B(sb + SMEM_B0 + (uint32_t)((t + 2) % NSTAGE) * B_TILE, t + 2, tid);

        const uint32_t aB = sb + a_off + (uint32_t)shifts[t] * ROWB;
        const uint32_t bB = sb + SMEM_B0 + (uint32_t)(t % NSTAGE) * B_TILE + b_off;
        #pragma unroll
        for (int ks = 0; ks < 4; ++ks) {
            uint32_t a[4][4];
            #pragma unroll
            for (int mf = 0; mf < 4; ++mf)
                ldm_x4(a[mf][0], a[mf][1], a[mf][2], a[mf][3], aB + mf * 16 * ROWB + ks * 32);
            #pragma unroll
            for (int nf2 = 0; nf2 < 4; ++nf2) {
                uint32_t bb[4];
                ldm_x4(bb[0], bb[1], bb[2], bb[3], bB + nf2 * 16 * ROWB + ks * 32);
                #pragma unroll
                for (int mf = 0; mf < 4; ++mf) {
                    mma16816(acc[mf][nf2 * 2 + 0], a[mf], bb[0], bb[1]);
                    mma16816(acc[mf][nf2 * 2 + 1], a[mf], bb[2], bb[3]);
                }
            }
        }
    }
    __syncthreads();   // protect smem reuse by epilogue

    // ---- epilogue: transpose through smem (bias folded) -> coalesced stores ----
    float* so = (float*)smem;   // [oc][136]
    #pragma unroll
    for (int mf = 0; mf < 4; ++mf)
        #pragma unroll
        for (int nf = 0; nf < 8; ++nf)
            #pragma unroll
            for (int c = 0; c < 4; ++c) {
                int oc = nwarp * 64 + nf * 8 + (lane & 3) * 2 + (c & 1);
                int m  = mwarp * 64 + mf * 16 + (lane >> 2) + (c & 2) * 4;
                so[oc * 136 + m] = acc[mf][nf][c] + bias_s[oc];
            }
    __syncthreads();

    const int m_ = tid;                  // 0..127 : pixel index
    const int h  = R0 + (m_ >> 6);
    const int w_ = C0 + (m_ & 63);
    float* ob = out + ((size_t)b * C_OUT) * HH * WW + (size_t)h * WW + w_;
    #pragma unroll 8
    for (int oc = 0; oc < C_OUT; ++oc)
        ob[(size_t)oc * HH * WW] = so[oc * 136 + m_];
}

// ---------------- launch ----------------
extern "C" void kernel_launch(void* const* d_in, const int* in_sizes, int n_in,
                              void* d_out, int out_size) {
    const float* x    = (const float*)d_in[0];
    const float* wgt  = (const float*)d_in[1];
    const float* bias = (const float*)d_in[2];
    float* out = (float*)d_out;

    {
        dim3 g(PW, BATCH + 1);          // y==BATCH rows do weight repack
        prep_fused<<<g, 256>>>(x, wgt);
    }
    cudaFuncSetAttribute(oct_mma_kernel, cudaFuncAttributeMaxDynamicSharedMemorySize, SMEM_MAIN);
    {
        dim3 g((HH / TR) * (WW / TC), BATCH);   // 128 tiles x 16 batches
        oct_mma_kernel<<<g, NTHREADS, SMEM_MAIN>>>(bias, out);
    }
}